// round 7
// baseline (speedup 1.0000x reference)
#include <cuda_runtime.h>
#include <cuda_fp16.h>
#include <math.h>
#include <stdint.h>

// HashEmbedder: 16-level 2D multires hash grid, 2 feats/level, T=2^19.
// Phase 1: build fp16 cell-packed corner table (16B per cell).
// Phase 2: persistent kernel; levels 0..4 (62.5KB of cells) are staged in
// shared memory once per block; levels 5..15 gathered from L2 via LDG.128.
// 4 threads/point, 4 levels/thread, MLP=4.

#define NLEV 16
#define TLOG2 19
#define TSIZE (1u << TLOG2)
#define HMASK ((1u << TLOG2) - 1u)
#define PRIME1 2654435761u
#define NSMEM 5            // levels served from shared memory

// Sum of res^2 over the 16 levels = 706,816 cells; margin for safety.
#define MAX_CELLS 710000
__device__ uint4 g_packed[MAX_CELLS];   // 16B per cell: h00,h10,h01,h11

struct Params {
    float resF[NLEV];
    int   resI[NLEV];
    int   off[NLEV + 1];
};

// ---------------------------------------------------------------------------
// Phase 1: build packed table. One thread per cell.
// ---------------------------------------------------------------------------
__global__ __launch_bounds__(256) void build_packed_kernel(
    const float* __restrict__ emb, Params pm, int total_cells)
{
    int i = blockIdx.x * blockDim.x + threadIdx.x;
    if (i >= total_cells) return;

    int l = 0;
#pragma unroll
    for (int k = 1; k < NLEV; ++k) l += (i >= pm.off[k]);

    int c   = i - pm.off[l];
    int res = pm.resI[l];
    int cy  = c / res;
    int cx  = c - cy * res;

    uint32_t ux0 = (uint32_t)cx;
    uint32_t ux1 = (uint32_t)(cx + 1);
    uint32_t yp0 = (uint32_t)cy * PRIME1;
    uint32_t yp1 = (uint32_t)(cy + 1) * PRIME1;

    uint32_t a00 = (ux0 ^ yp0) & HMASK;
    uint32_t a10 = (ux1 ^ yp0) & HMASK;
    uint32_t a01 = (ux0 ^ yp1) & HMASK;
    uint32_t a11 = (ux1 ^ yp1) & HMASK;

    const float2* __restrict__ tab =
        ((const float2*)emb) + ((size_t)l << TLOG2);

    float2 f00 = __ldg(tab + a00);
    float2 f10 = __ldg(tab + a10);
    float2 f01 = __ldg(tab + a01);
    float2 f11 = __ldg(tab + a11);

    half2 h00 = __float22half2_rn(f00);
    half2 h10 = __float22half2_rn(f10);
    half2 h01 = __float22half2_rn(f01);
    half2 h11 = __float22half2_rn(f11);

    uint4 r;
    r.x = *(const uint32_t*)&h00;
    r.y = *(const uint32_t*)&h10;
    r.z = *(const uint32_t*)&h01;
    r.w = *(const uint32_t*)&h11;
    g_packed[i] = r;
}

// ---------------------------------------------------------------------------
// Phase 2: persistent; SMEM-staged coarse levels + LDG fine levels.
// ---------------------------------------------------------------------------
#define BLK 512
#define PPB (BLK / 4)       // points per block iteration

__global__ __launch_bounds__(BLK, 3) void hash_embed_kernel(
    const float* __restrict__ x,
    float* __restrict__ out,
    int n_points,
    Params pm,
    int smem_cells)
{
    extern __shared__ uint4 s_cells[];

    __shared__ float s_resF[NLEV];
    __shared__ int   s_resI[NLEV];
    __shared__ int   s_off[NLEV];
    if (threadIdx.x < NLEV) {
        s_resF[threadIdx.x] = pm.resF[threadIdx.x];
        s_resI[threadIdx.x] = pm.resI[threadIdx.x];
        s_off[threadIdx.x]  = pm.off[threadIdx.x];
    }
    // Stage coarse-level cell records (contiguous prefix of g_packed).
    for (int i = threadIdx.x; i < smem_cells; i += BLK)
        s_cells[i] = g_packed[i];
    __syncthreads();

    int tsub = threadIdx.x & 3;       // which 4-level group
    int lb   = tsub << 2;             // base level: 0,4,8,12
    int trow = threadIdx.x >> 2;      // point row within block

    for (int base = blockIdx.x * PPB; base < n_points; base += gridDim.x * PPB) {
        int p = base + trow;
        if (p >= n_points) break;

        float2 xy = __ldg(((const float2*)x) + p);

        int idx[4];
#pragma unroll
        for (int j = 0; j < 4; ++j) {
            int   l   = lb + j;
            float res = s_resF[l];
            int   ri  = s_resI[l];
            int   off = s_off[l];

            int ix = min(max((int)floorf(xy.x * res), 0), ri - 1);
            int iy = min(max((int)floorf(xy.y * res), 0), ri - 1);
            idx[j] = off + iy * ri + ix;
        }

        // 4 independent fetches: SMEM for levels < NSMEM, else global.
        uint4 rr[4];
#pragma unroll
        for (int j = 0; j < 4; ++j) {
            if (lb + j < NSMEM) rr[j] = s_cells[idx[j]];
            else                rr[j] = __ldg(&g_packed[idx[j]]);
        }

        float o[8];
#pragma unroll
        for (int j = 0; j < 4; ++j) {
            float res = s_resF[lb + j];
            float px = xy.x * res;
            float py = xy.y * res;
            float wx = px - floorf(px);
            float wy = py - floorf(py);

            float2 f00 = __half22float2(*(const half2*)&rr[j].x);
            float2 f10 = __half22float2(*(const half2*)&rr[j].y);
            float2 f01 = __half22float2(*(const half2*)&rr[j].z);
            float2 f11 = __half22float2(*(const half2*)&rr[j].w);

            float u = 1.0f - wx;
            float v = 1.0f - wy;

            o[2 * j]     = (f00.x * u + f10.x * wx) * v + (f01.x * u + f11.x * wx) * wy;
            o[2 * j + 1] = (f00.y * u + f10.y * wx) * v + (f01.y * u + f11.y * wx) * wy;
        }

        // thread covers floats [lb*2, lb*2+8) of point row p -> 32B.
        float4* dst = (float4*)(out + (size_t)p * (NLEV * 2) + lb * 2);
        dst[0] = make_float4(o[0], o[1], o[2], o[3]);
        dst[1] = make_float4(o[4], o[5], o[6], o[7]);
    }
}

extern "C" void kernel_launch(void* const* d_in, const int* in_sizes, int n_in,
                              void* d_out, int out_size)
{
    const float* x   = (const float*)d_in[0];
    const float* emb = (const float*)d_in[1];
    float* out       = (float*)d_out;

    int n_points = in_sizes[0] / 2;

    Params pm;
    double b = exp((log(512.0) - log(16.0)) / 15.0);
    int acc = 0;
    for (int l = 0; l < NLEV; ++l) {
        double r = floor(16.0 * pow(b, (double)l));
        pm.resF[l] = (float)r;
        pm.resI[l] = (int)r;
        pm.off[l]  = acc;
        acc += pm.resI[l] * pm.resI[l];
    }
    pm.off[NLEV] = acc;

    int smem_cells = pm.off[NSMEM];                  // cells in levels 0..4
    size_t smem_bytes = (size_t)smem_cells * 16;     // ~62.5 KB

    // Phase 1: build packed corner table (fp16, 16B per cell)
    {
        int threads = 256;
        int blocks = (acc + threads - 1) / threads;
        build_packed_kernel<<<blocks, threads>>>(emb, pm, acc);
    }

    // Phase 2: persistent gather + lerp
    {
        cudaFuncSetAttribute(hash_embed_kernel,
                             cudaFuncAttributeMaxDynamicSharedMemorySize,
                             (int)smem_bytes);
        int nsm = 148;
        cudaDeviceGetAttribute(&nsm, cudaDevAttrMultiProcessorCount, 0);
        int blocks = nsm * 3;
        hash_embed_kernel<<<blocks, BLK, smem_bytes>>>(x, out, n_points, pm,
                                                       smem_cells);
    }
}